// round 1
// baseline (speedup 1.0000x reference)
#include <cuda_runtime.h>

// CTRNN forward scan on GB300.
// Inputs (metadata order): x[B,T,D] f32, seq_lengths[B] i32 (forward no-op),
// W_in[H,D] f32, b_in[H] f32, W_hh[H,H] f32, b_hh[H] f32.
// Output: outputs[B,T,H] followed by h_last[B,H], both f32, concatenated flat.

#define BB 256
#define TT 2048
#define DD 32
#define HH 64

typedef unsigned long long u64;

__device__ __forceinline__ u64 pack2(float lo, float hi) {
    u64 r; asm("mov.b64 %0, {%1, %2};" : "=l"(r) : "f"(lo), "f"(hi)); return r;
}
__device__ __forceinline__ float2 unpack2(u64 v) {
    float2 f; asm("mov.b64 {%0, %1}, %2;" : "=f"(f.x), "=f"(f.y) : "l"(v)); return f;
}
// Packed fp32x2 FMA (Blackwell FFMA2): d = a*b + d, two fp32 lanes per issue.
__device__ __forceinline__ void ffma2(u64& d, u64 a, u64 b) {
    asm("fma.rn.f32x2 %0, %1, %2, %0;" : "+l"(d) : "l"(a), "l"(b));
}
__device__ __forceinline__ u64 add2(u64 a, u64 b) {
    u64 r; asm("add.rn.f32x2 %0, %1, %2;" : "=l"(r) : "l"(a), "l"(b)); return r;
}

__global__ void __launch_bounds__(HH) ctrnn_scan_kernel(
    const float* __restrict__ x,
    const float* __restrict__ W_in,
    const float* __restrict__ b_in,
    const float* __restrict__ W_hh,
    const float* __restrict__ b_hh,
    float* __restrict__ out)
{
    const int b = blockIdx.x;   // batch element
    const int j = threadIdx.x;  // hidden unit owned by this thread

    __shared__ __align__(16) float hbuf[2][HH];  // double-buffered hidden state
    __shared__ __align__(16) float xbuf[2][DD];  // double-buffered x[t,:]

    // --- Load W_hh row j and W_in row j into registers, packed as f32x2 pairs ---
    u64 w[HH / 2];
    {
        const float4* wr = (const float4*)(W_hh + j * HH);
        #pragma unroll
        for (int i = 0; i < HH / 4; i++) {
            float4 v = wr[i];
            w[2 * i]     = pack2(v.x, v.y);
            w[2 * i + 1] = pack2(v.z, v.w);
        }
    }
    u64 wi[DD / 2];
    {
        const float4* wr = (const float4*)(W_in + j * DD);
        #pragma unroll
        for (int i = 0; i < DD / 4; i++) {
            float4 v = wr[i];
            wi[2 * i]     = pack2(v.x, v.y);
            wi[2 * i + 1] = pack2(v.z, v.w);
        }
    }

    const float bias  = b_in[j] + b_hh[j];
    const float ALPHA = (float)(16.67 / 40.0);
    const float OMA   = (float)(1.0 - 16.67 / 40.0);

    // --- Prologue: h0 = 0, stage x[b,0,:] ---
    const float4* xg = (const float4*)(x + (size_t)b * TT * DD);
    hbuf[0][j] = 0.0f;
    if (j < DD / 4) ((float4*)xbuf[0])[j] = xg[j];
    __syncthreads();

    float hold = 0.0f;
    float* outb = out + (size_t)b * TT * HH;

    for (int t = 0; t < TT; t++) {
        const int cur = t & 1;
        const int nxt = cur ^ 1;

        // Prefetch x[b, t+1, :] early so global latency overlaps the dots.
        float4 xr = make_float4(0.f, 0.f, 0.f, 0.f);
        if (j < DD / 4 && t + 1 < TT) xr = xg[(size_t)(t + 1) * (DD / 4) + j];

        // --- h(t-1) . W_hh[j,:]  (64 MACs = 32 FFMA2, 4 independent accumulators) ---
        u64 a0 = 0, a1 = 0, a2 = 0, a3 = 0;
        const ulonglong2* hv = (const ulonglong2*)hbuf[cur];  // broadcast LDS.128
        #pragma unroll
        for (int i = 0; i < HH / 4; i++) {
            ulonglong2 hq = hv[i];
            if (i & 1) { ffma2(a2, hq.x, w[2 * i]); ffma2(a3, hq.y, w[2 * i + 1]); }
            else       { ffma2(a0, hq.x, w[2 * i]); ffma2(a1, hq.y, w[2 * i + 1]); }
        }

        // --- x(t) . W_in[j,:]  (32 MACs = 16 FFMA2) ---
        u64 c0 = 0, c1 = 0;
        const ulonglong2* xv = (const ulonglong2*)xbuf[cur];
        #pragma unroll
        for (int i = 0; i < DD / 4; i++) {
            ulonglong2 xq = xv[i];
            ffma2(c0, xq.x, wi[2 * i]);
            ffma2(c1, xq.y, wi[2 * i + 1]);
        }

        // --- Reduce + pointwise update ---
        u64 s = add2(add2(add2(a0, a1), add2(a2, a3)), add2(c0, c1));
        float2 sf = unpack2(s);
        float pre  = sf.x + sf.y + bias;
        float hnew = fmaxf(fmaf(hold, OMA, pre * ALPHA), 0.0f);

        outb[(size_t)t * HH + j] = hnew;

        // Publish next state. Buffer `nxt` was last read in step t-1, whose
        // reads are separated from these writes by step t-1's barrier.
        hbuf[nxt][j] = hnew;
        if (j < DD / 4 && t + 1 < TT) ((float4*)xbuf[nxt])[j] = xr;
        hold = hnew;
        __syncthreads();  // single barrier per step (double-buffered)
    }

    // h_last appended after outputs
    out[(size_t)BB * TT * HH + (size_t)b * HH + j] = hold;
}

extern "C" void kernel_launch(void* const* d_in, const int* in_sizes, int n_in,
                              void* d_out, int out_size) {
    (void)in_sizes; (void)n_in; (void)out_size;
    const float* x    = (const float*)d_in[0];
    // d_in[1] = seq_lengths: forward no-op (mask only gates gradients)
    const float* W_in = (const float*)d_in[2];
    const float* b_in = (const float*)d_in[3];
    const float* W_hh = (const float*)d_in[4];
    const float* b_hh = (const float*)d_in[5];

    ctrnn_scan_kernel<<<BB, HH>>>(x, W_in, b_in, W_hh, b_hh, (float*)d_out);
}

// round 5
// speedup vs baseline: 1.3641x; 1.3641x over previous
#include <cuda_runtime.h>

// CTRNN forward scan on GB300 — round 2: depth-8 software-pipelined x prefetch.
// Inputs (metadata order): x[B,T,D] f32, seq_lengths[B] i32 (forward no-op),
// W_in[H,D] f32, b_in[H] f32, W_hh[H,H] f32, b_hh[H] f32.
// Output: outputs[B,T,H] then h_last[B,H], f32, concatenated flat.

#define BB 256
#define TT 2048
#define DD 32
#define HH 64
#define PF 8   // x prefetch depth (steps); TT % PF == 0

typedef unsigned long long u64;

__device__ __forceinline__ u64 pack2(float lo, float hi) {
    u64 r; asm("mov.b64 %0, {%1, %2};" : "=l"(r) : "f"(lo), "f"(hi)); return r;
}
__device__ __forceinline__ float2 unpack2(u64 v) {
    float2 f; asm("mov.b64 {%0, %1}, %2;" : "=f"(f.x), "=f"(f.y) : "l"(v)); return f;
}
// Packed fp32x2 FMA (Blackwell FFMA2): d = a*b + d, two fp32 lanes per issue.
__device__ __forceinline__ void ffma2(u64& d, u64 a, u64 b) {
    asm("fma.rn.f32x2 %0, %1, %2, %0;" : "+l"(d) : "l"(a), "l"(b));
}
__device__ __forceinline__ u64 add2(u64 a, u64 b) {
    u64 r; asm("add.rn.f32x2 %0, %1, %2;" : "=l"(r) : "l"(a), "l"(b)); return r;
}
__device__ __forceinline__ u64 mul2(u64 a, u64 b) {
    u64 r; asm("mul.rn.f32x2 %0, %1, %2;" : "=l"(r) : "l"(a), "l"(b)); return r;
}

__global__ void __launch_bounds__(HH) ctrnn_scan_kernel(
    const float* __restrict__ x,
    const float* __restrict__ W_in,
    const float* __restrict__ b_in,
    const float* __restrict__ W_hh,
    const float* __restrict__ b_hh,
    float* __restrict__ out)
{
    const int b = blockIdx.x;   // batch element
    const int j = threadIdx.x;  // hidden unit owned by this thread

    __shared__ __align__(16) float hbuf[2][HH];  // double-buffered hidden state
    __shared__ __align__(16) float xbuf[2][DD];  // double-buffered x[t,:]

    const float ALPHA = (float)(16.67 / 40.0);
    const float OMA   = (float)(1.0 - 16.67 / 40.0);
    const u64   ALPHA2 = pack2(ALPHA, ALPHA);

    // --- W_hh row j and W_in row j in registers, pre-scaled by ALPHA ---
    u64 w[HH / 2];
    {
        const float4* wr = (const float4*)(W_hh + j * HH);
        #pragma unroll
        for (int i = 0; i < HH / 4; i++) {
            float4 v = wr[i];
            w[2 * i]     = mul2(pack2(v.x, v.y), ALPHA2);
            w[2 * i + 1] = mul2(pack2(v.z, v.w), ALPHA2);
        }
    }
    u64 wi[DD / 2];
    {
        const float4* wr = (const float4*)(W_in + j * DD);
        #pragma unroll
        for (int i = 0; i < DD / 4; i++) {
            float4 v = wr[i];
            wi[2 * i]     = mul2(pack2(v.x, v.y), ALPHA2);
            wi[2 * i + 1] = mul2(pack2(v.z, v.w), ALPHA2);
        }
    }

    const float biasA = ALPHA * (b_in[j] + b_hh[j]);   // folded, pre-scaled bias

    // --- x prefetch ring: warp-0 lanes (j < 32) own one float per slot ---
    const float* xg = x + (size_t)b * TT * DD;
    float xr[PF];
    if (j < DD) {
        #pragma unroll
        for (int p = 0; p < PF; p++) xr[p] = xg[p * DD + j];
    }

    // Prologue: h0 = 0, stage x[0] into slot 0, reload ring slot 0 with x[PF].
    hbuf[0][j] = 0.0f;
    if (j < DD) {
        xbuf[0][j] = xr[0];
        xr[0] = xg[PF * DD + j];
    }
    __syncthreads();

    float hold = 0.0f;
    float* outb = out + (size_t)b * TT * HH;

    for (int t0 = 0; t0 < TT; t0 += PF) {
        #pragma unroll
        for (int p = 0; p < PF; p++) {
            const int t   = t0 + p;
            const int cur = t & 1;
            const int nxt = cur ^ 1;
            const int q   = (p + 1) % PF;   // compile-time ring index

            // --- h(t-1) . (ALPHA*W_hh[j,:]) : 32 FFMA2, 4 accumulators ---
            u64 a0 = pack2(biasA, 0.0f);    // bias seeded into accumulator
            u64 a1 = 0, a2 = 0, a3 = 0;
            const ulonglong2* hv = (const ulonglong2*)hbuf[cur];  // broadcast LDS.128
            #pragma unroll
            for (int i = 0; i < HH / 4; i++) {
                ulonglong2 hq = hv[i];
                if (i & 1) { ffma2(a2, hq.x, w[2 * i]); ffma2(a3, hq.y, w[2 * i + 1]); }
                else       { ffma2(a0, hq.x, w[2 * i]); ffma2(a1, hq.y, w[2 * i + 1]); }
            }

            // --- x(t) . (ALPHA*W_in[j,:]) : 16 FFMA2 ---
            u64 c0 = 0, c1 = 0;
            const ulonglong2* xv = (const ulonglong2*)xbuf[cur];
            #pragma unroll
            for (int i = 0; i < DD / 4; i++) {
                ulonglong2 xq = xv[i];
                ffma2(c0, xq.x, wi[2 * i]);
                ffma2(c1, xq.y, wi[2 * i + 1]);
            }

            // --- reduce + pointwise update ---
            u64 s = add2(add2(add2(a0, a1), add2(a2, a3)), add2(c0, c1));
            float2 sf = unpack2(s);
            float hnew = fmaxf(fmaf(hold, OMA, sf.x + sf.y), 0.0f);

            outb[(size_t)t * HH + j] = hnew;

            // Publish next state + stage x(t+1); reload ring slot with x(t+1+PF).
            hbuf[nxt][j] = hnew;
            if (j < DD) {
                xbuf[nxt][j] = xr[q];          // x(t+1) -> smem (garbage at t=TT-1, unused)
                const int tl = t + 1 + PF;
                if (tl < TT) xr[q] = xg[(size_t)tl * DD + j];
            }
            hold = hnew;
            __syncthreads();  // single barrier per step (double-buffered)
        }
    }

    // h_last appended after outputs
    out[(size_t)BB * TT * HH + (size_t)b * HH + j] = hold;
}

extern "C" void kernel_launch(void* const* d_in, const int* in_sizes, int n_in,
                              void* d_out, int out_size) {
    (void)in_sizes; (void)n_in; (void)out_size;
    const float* x    = (const float*)d_in[0];
    // d_in[1] = seq_lengths: forward no-op (mask only gates gradients)
    const float* W_in = (const float*)d_in[2];
    const float* b_in = (const float*)d_in[3];
    const float* W_hh = (const float*)d_in[4];
    const float* b_hh = (const float*)d_in[5];

    ctrnn_scan_kernel<<<BB, HH>>>(x, W_in, b_in, W_hh, b_hh, (float*)d_out);
}

// round 6
// speedup vs baseline: 1.6114x; 1.1813x over previous
#include <cuda_runtime.h>

// CTRNN forward on GB300 — round 3: warp-synchronous scan (no CTA barrier),
// input projection hoisted into a separate pass with __device__ scratch.
// Inputs (metadata order): x[B,T,D] f32, seq_lengths[B] i32 (forward no-op),
// W_in[H,D] f32, b_in[H] f32, W_hh[H,H] f32, b_hh[H] f32.
// Output: outputs[B,T,H] then h_last[B,H], f32, concatenated flat.

#define BB 256
#define TT 2048
#define DD 32
#define HH 64
#define PF 8   // xp prefetch depth (steps); TT % PF == 0

typedef unsigned long long u64;

// 128 MB scratch for xp = ALPHA * (x @ W_in^T + b_in + b_hh), layout [B][T][H].
__device__ __align__(16) float g_xp[(size_t)BB * TT * HH];

__device__ __forceinline__ u64 pack2(float lo, float hi) {
    u64 r; asm("mov.b64 %0, {%1, %2};" : "=l"(r) : "f"(lo), "f"(hi)); return r;
}
__device__ __forceinline__ float2 unpack2(u64 v) {
    float2 f; asm("mov.b64 {%0, %1}, %2;" : "=f"(f.x), "=f"(f.y) : "l"(v)); return f;
}
// Packed fp32x2 FMA (Blackwell FFMA2): d = a*b + d.
__device__ __forceinline__ void ffma2(u64& d, u64 a, u64 b) {
    asm("fma.rn.f32x2 %0, %1, %2, %0;" : "+l"(d) : "l"(a), "l"(b));
}
__device__ __forceinline__ u64 add2(u64 a, u64 b) {
    u64 r; asm("add.rn.f32x2 %0, %1, %2;" : "=l"(r) : "l"(a), "l"(b)); return r;
}

#define ALPHA_F ((float)(16.67 / 40.0))
#define OMA_F   ((float)(1.0 - 16.67 / 40.0))

// ---------------- Pass 1: xp[b,t,j] = ALPHA*(x[b,t,:] . W_in[j,:] + b_in[j] + b_hh[j])
// Grid BB, block 128 (4 warps). Warp w handles t = w, w+4, ... Lane l owns pair (2l,2l+1).
__global__ void __launch_bounds__(128) xproj_kernel(
    const float* __restrict__ x,
    const float* __restrict__ W_in,
    const float* __restrict__ b_in,
    const float* __restrict__ b_hh)
{
    const int b    = blockIdx.x;
    const int warp = threadIdx.x >> 5;
    const int l    = threadIdx.x & 31;
    const int j0   = 2 * l, j1 = 2 * l + 1;

    // Packed weights: wip[k] = (ALPHA*W_in[j0][k], ALPHA*W_in[j1][k])
    u64 wip[DD];
    {
        const float4* r0 = (const float4*)(W_in + j0 * DD);
        const float4* r1 = (const float4*)(W_in + j1 * DD);
        #pragma unroll
        for (int k4 = 0; k4 < DD / 4; k4++) {
            float4 a = r0[k4], c = r1[k4];
            wip[4 * k4 + 0] = pack2(ALPHA_F * a.x, ALPHA_F * c.x);
            wip[4 * k4 + 1] = pack2(ALPHA_F * a.y, ALPHA_F * c.y);
            wip[4 * k4 + 2] = pack2(ALPHA_F * a.z, ALPHA_F * c.z);
            wip[4 * k4 + 3] = pack2(ALPHA_F * a.w, ALPHA_F * c.w);
        }
    }
    const u64 bias = pack2(ALPHA_F * (b_in[j0] + b_hh[j0]),
                           ALPHA_F * (b_in[j1] + b_hh[j1]));

    u64* xpb = (u64*)(g_xp + (size_t)b * TT * HH);

    for (int t = warp; t < TT; t += 4) {
        const float4* xrow = (const float4*)(x + ((size_t)b * TT + t) * DD);
        u64 a0 = bias, a1 = 0;
        #pragma unroll
        for (int k4 = 0; k4 < DD / 4; k4++) {
            float4 xv = xrow[k4];  // uniform address -> broadcast load
            ffma2(a0, pack2(xv.x, xv.x), wip[4 * k4 + 0]);
            ffma2(a1, pack2(xv.y, xv.y), wip[4 * k4 + 1]);
            ffma2(a0, pack2(xv.z, xv.z), wip[4 * k4 + 2]);
            ffma2(a1, pack2(xv.w, xv.w), wip[4 * k4 + 3]);
        }
        xpb[(size_t)t * 32 + l] = add2(a0, a1);  // coalesced STG.64
    }
}

// ---------------- Pass 2: warp-synchronous scan. One warp per batch.
__global__ void __launch_bounds__(32) ctrnn_scan_kernel(
    const float* __restrict__ W_hh,
    float* __restrict__ out)
{
    const int b  = blockIdx.x;
    const int l  = threadIdx.x;
    const int j0 = 2 * l, j1 = 2 * l + 1;

    // Duplicated hidden state: hdup[buf][k] = (h[k], h[k]); double-buffered.
    __shared__ __align__(16) u64 hdup[2][HH];

    // wp[k] = (ALPHA*W_hh[j0][k], ALPHA*W_hh[j1][k]) : 64 u64 = 128 regs
    u64 wp[HH];
    {
        const float4* r0 = (const float4*)(W_hh + j0 * HH);
        const float4* r1 = (const float4*)(W_hh + j1 * HH);
        #pragma unroll
        for (int k4 = 0; k4 < HH / 4; k4++) {
            float4 a = r0[k4], c = r1[k4];
            wp[4 * k4 + 0] = pack2(ALPHA_F * a.x, ALPHA_F * c.x);
            wp[4 * k4 + 1] = pack2(ALPHA_F * a.y, ALPHA_F * c.y);
            wp[4 * k4 + 2] = pack2(ALPHA_F * a.z, ALPHA_F * c.z);
            wp[4 * k4 + 3] = pack2(ALPHA_F * a.w, ALPHA_F * c.w);
        }
    }

    // xp prefetch ring: one u64 pair per lane per step.
    const u64* xpb = (const u64*)(g_xp + (size_t)b * TT * HH);
    u64 xr[PF];
    #pragma unroll
    for (int p = 0; p < PF; p++) xr[p] = xpb[(size_t)p * 32 + l];

    // h0 = 0
    hdup[0][j0] = 0ull;
    hdup[0][j1] = 0ull;
    u64 hpair = 0ull;
    const u64 OMA2 = pack2(OMA_F, OMA_F);
    __syncwarp();

    u64* outb = (u64*)(out + (size_t)b * TT * HH);

    for (int t0 = 0; t0 < TT; t0 += PF) {
        #pragma unroll
        for (int p = 0; p < PF; p++) {
            const int t   = t0 + p;
            const int cur = t & 1;
            const int nxt = cur ^ 1;

            // acc = xp(t) + h(t-1).(ALPHA*W_hh rows j0,j1), packed per output pair
            u64 a0 = xr[p], a1 = 0, a2 = 0, a3 = 0;
            const ulonglong2* hv = (const ulonglong2*)hdup[cur];  // broadcast LDS.128
            #pragma unroll
            for (int i = 0; i < HH / 2; i++) {     // 32 x LDS.128, 64 x ffma2
                ulonglong2 hq = hv[i];
                if (i & 1) { ffma2(a2, hq.x, wp[2 * i]); ffma2(a3, hq.y, wp[2 * i + 1]); }
                else       { ffma2(a0, hq.x, wp[2 * i]); ffma2(a1, hq.y, wp[2 * i + 1]); }
            }
            u64 s = add2(add2(a0, a1), add2(a2, a3));
            ffma2(s, hpair, OMA2);                 // s = OMA*h + acc

            float2 sf = unpack2(s);
            float h0 = fmaxf(sf.x, 0.0f);
            float h1 = fmaxf(sf.y, 0.0f);
            hpair = pack2(h0, h1);

            outb[(size_t)t * 32 + l] = hpair;      // coalesced STG.64

            // Publish duplicated next state: (h0,h0),(h1,h1) as one STS.128
            ulonglong2 dup;
            dup.x = pack2(h0, h0);
            dup.y = pack2(h1, h1);
            *(ulonglong2*)&hdup[nxt][j0] = dup;

            // Refill ring slot with xp(t+PF)
            const int tl = t + PF;
            if (tl < TT) xr[p] = xpb[(size_t)tl * 32 + l];

            __syncwarp();                          // only sync in the step
        }
    }

    // h_last appended after outputs
    ((u64*)(out + (size_t)BB * TT * HH))[(size_t)b * 32 + l] = hpair;
}

extern "C" void kernel_launch(void* const* d_in, const int* in_sizes, int n_in,
                              void* d_out, int out_size) {
    (void)in_sizes; (void)n_in; (void)out_size;
    const float* x    = (const float*)d_in[0];
    // d_in[1] = seq_lengths: forward no-op (mask only gates gradients)
    const float* W_in = (const float*)d_in[2];
    const float* b_in = (const float*)d_in[3];
    const float* W_hh = (const float*)d_in[4];
    const float* b_hh = (const float*)d_in[5];
    float* out = (float*)d_out;

    xproj_kernel<<<BB, 128>>>(x, W_in, b_in, b_hh);
    ctrnn_scan_kernel<<<BB, 32>>>(W_hh, out);
}

// round 7
// speedup vs baseline: 2.1287x; 1.3210x over previous
#include <cuda_runtime.h>

// CTRNN forward on GB300 — round 4: massively parallel input-projection pass
// + warp-synchronous scan (1 warp per batch, no CTA barrier).
// Inputs (metadata order): x[B,T,D] f32, seq_lengths[B] i32 (forward no-op),
// W_in[H,D] f32, b_in[H] f32, W_hh[H,H] f32, b_hh[H] f32.
// Output: outputs[B,T,H] then h_last[B,H], f32, concatenated flat.

#define BB 256
#define TT 2048
#define DD 32
#define HH 64
#define PF 8   // xp prefetch depth (steps); TT % PF == 0

typedef unsigned long long u64;

// Scratch for xp = ALPHA*(x@W_in^T + b_in + b_hh), [B][T][H], padded by PF rows
// so the scan's ring refill can load unconditionally (pad contents unused).
__device__ __align__(16) float g_xp[(size_t)BB * TT * HH + PF * HH];

__device__ __forceinline__ u64 pack2(float lo, float hi) {
    u64 r; asm("mov.b64 %0, {%1, %2};" : "=l"(r) : "f"(lo), "f"(hi)); return r;
}
__device__ __forceinline__ float2 unpack2(u64 v) {
    float2 f; asm("mov.b64 {%0, %1}, %2;" : "=f"(f.x), "=f"(f.y) : "l"(v)); return f;
}
// Packed fp32x2 FMA (Blackwell FFMA2): d = a*b + d.
__device__ __forceinline__ void ffma2(u64& d, u64 a, u64 b) {
    asm("fma.rn.f32x2 %0, %1, %2, %0;" : "+l"(d) : "l"(a), "l"(b));
}
__device__ __forceinline__ u64 add2(u64 a, u64 b) {
    u64 r; asm("add.rn.f32x2 %0, %1, %2;" : "=l"(r) : "l"(a), "l"(b)); return r;
}

#define ALPHA_F ((float)(16.67 / 40.0))
#define OMA_F   ((float)(1.0 - 16.67 / 40.0))

#define XP_CTAS    2048
#define XP_THREADS 256
#define XP_WARPS   (XP_CTAS * XP_THREADS / 32)   // 16384 warps
#define XP_ROWS    (BB * TT)                     // 524288 rows

// ---------------- Pass 1: xp[r,j] = ALPHA*(x[r,:] . W_in[j,:] + b_in[j] + b_hh[j])
// One warp per row (grid-stride, 2 rows in flight for MLP). Lane l owns pair (2l,2l+1).
__global__ void __launch_bounds__(XP_THREADS) xproj_kernel(
    const float* __restrict__ x,
    const float* __restrict__ W_in,
    const float* __restrict__ b_in,
    const float* __restrict__ b_hh)
{
    const int gwarp = (blockIdx.x * XP_THREADS + threadIdx.x) >> 5;
    const int l     = threadIdx.x & 31;
    const int j0    = 2 * l, j1 = 2 * l + 1;

    // wip[k] = (ALPHA*W_in[j0][k], ALPHA*W_in[j1][k])
    u64 wip[DD];
    {
        const float4* r0 = (const float4*)(W_in + j0 * DD);
        const float4* r1 = (const float4*)(W_in + j1 * DD);
        #pragma unroll
        for (int k4 = 0; k4 < DD / 4; k4++) {
            float4 a = r0[k4], c = r1[k4];
            wip[4 * k4 + 0] = pack2(ALPHA_F * a.x, ALPHA_F * c.x);
            wip[4 * k4 + 1] = pack2(ALPHA_F * a.y, ALPHA_F * c.y);
            wip[4 * k4 + 2] = pack2(ALPHA_F * a.z, ALPHA_F * c.z);
            wip[4 * k4 + 3] = pack2(ALPHA_F * a.w, ALPHA_F * c.w);
        }
    }
    const u64 bias = pack2(ALPHA_F * (b_in[j0] + b_hh[j0]),
                           ALPHA_F * (b_in[j1] + b_hh[j1]));

    u64* xpw = (u64*)g_xp;

    // Two rows per iteration for memory-level parallelism.
    for (int r = gwarp; r < XP_ROWS; r += 2 * XP_WARPS) {
        const int r2 = r + XP_WARPS;
        const float4* xa = (const float4*)(x + (size_t)r  * DD);
        const float4* xb = (const float4*)(x + (size_t)r2 * DD);

        u64 a0 = bias, a1 = 0, c0 = bias, c1 = 0;
        #pragma unroll
        for (int k4 = 0; k4 < DD / 4; k4++) {
            float4 va = xa[k4];                          // uniform -> broadcast
            ffma2(a0, pack2(va.x, va.x), wip[4 * k4 + 0]);
            ffma2(a1, pack2(va.y, va.y), wip[4 * k4 + 1]);
            ffma2(a0, pack2(va.z, va.z), wip[4 * k4 + 2]);
            ffma2(a1, pack2(va.w, va.w), wip[4 * k4 + 3]);
        }
        #pragma unroll
        for (int k4 = 0; k4 < DD / 4; k4++) {
            float4 vb = xb[k4];
            ffma2(c0, pack2(vb.x, vb.x), wip[4 * k4 + 0]);
            ffma2(c1, pack2(vb.y, vb.y), wip[4 * k4 + 1]);
            ffma2(c0, pack2(vb.z, vb.z), wip[4 * k4 + 2]);
            ffma2(c1, pack2(vb.w, vb.w), wip[4 * k4 + 3]);
        }
        xpw[(size_t)r  * 32 + l] = add2(a0, a1);         // coalesced STG.64
        xpw[(size_t)r2 * 32 + l] = add2(c0, c1);
    }
}

// ---------------- Pass 2: warp-synchronous scan. One warp per batch.
__global__ void __launch_bounds__(32) ctrnn_scan_kernel(
    const float* __restrict__ W_hh,
    float* __restrict__ out)
{
    const int b  = blockIdx.x;
    const int l  = threadIdx.x;
    const int j0 = 2 * l, j1 = 2 * l + 1;

    // Duplicated hidden state: hdup[buf][k] = (h[k], h[k]); double-buffered.
    __shared__ __align__(16) u64 hdup[2][HH];

    // wp[k] = (ALPHA*W_hh[j0][k], ALPHA*W_hh[j1][k]) : 64 u64 = 128 regs
    u64 wp[HH];
    {
        const float4* r0 = (const float4*)(W_hh + j0 * HH);
        const float4* r1 = (const float4*)(W_hh + j1 * HH);
        #pragma unroll
        for (int k4 = 0; k4 < HH / 4; k4++) {
            float4 a = r0[k4], c = r1[k4];
            wp[4 * k4 + 0] = pack2(ALPHA_F * a.x, ALPHA_F * c.x);
            wp[4 * k4 + 1] = pack2(ALPHA_F * a.y, ALPHA_F * c.y);
            wp[4 * k4 + 2] = pack2(ALPHA_F * a.z, ALPHA_F * c.z);
            wp[4 * k4 + 3] = pack2(ALPHA_F * a.w, ALPHA_F * c.w);
        }
    }

    // xp prefetch ring: one u64 pair per lane per step.
    const u64* xpb = (const u64*)(g_xp + (size_t)b * TT * HH);
    u64 xr[PF];
    #pragma unroll
    for (int p = 0; p < PF; p++) xr[p] = xpb[(size_t)p * 32 + l];

    // h0 = 0
    hdup[0][j0] = 0ull;
    hdup[0][j1] = 0ull;
    u64 hpair = 0ull;
    const u64 OMA2 = pack2(OMA_F, OMA_F);
    __syncwarp();

    u64* outb = (u64*)(out + (size_t)b * TT * HH);

    for (int t0 = 0; t0 < TT; t0 += PF) {
        #pragma unroll
        for (int p = 0; p < PF; p++) {
            const int t   = t0 + p;
            const int cur = t & 1;
            const int nxt = cur ^ 1;

            // acc = xp(t) + h(t-1).(ALPHA*W_hh rows j0,j1), packed per output pair
            u64 a0 = xr[p], a1 = 0, a2 = 0, a3 = 0;
            const ulonglong2* hv = (const ulonglong2*)hdup[cur];  // broadcast LDS.128
            #pragma unroll
            for (int i = 0; i < HH / 2; i++) {     // 32 x LDS.128, 64 x ffma2
                ulonglong2 hq = hv[i];
                if (i & 1) { ffma2(a2, hq.x, wp[2 * i]); ffma2(a3, hq.y, wp[2 * i + 1]); }
                else       { ffma2(a0, hq.x, wp[2 * i]); ffma2(a1, hq.y, wp[2 * i + 1]); }
            }
            u64 s = add2(add2(a0, a1), add2(a2, a3));
            ffma2(s, hpair, OMA2);                 // s = OMA*h + acc

            float2 sf = unpack2(s);
            float h0 = fmaxf(sf.x, 0.0f);
            float h1 = fmaxf(sf.y, 0.0f);
            hpair = pack2(h0, h1);

            outb[(size_t)t * 32 + l] = hpair;      // coalesced STG.64

            // Publish duplicated next state: (h0,h0),(h1,h1) as one STS.128
            ulonglong2 dup;
            dup.x = pack2(h0, h0);
            dup.y = pack2(h1, h1);
            *(ulonglong2*)&hdup[nxt][j0] = dup;

            // Refill ring slot with xp(t+PF). Unconditional: g_xp is padded by
            // PF rows, and values loaded past TT are never consumed.
            xr[p] = xpb[(size_t)(t + PF) * 32 + l];

            __syncwarp();                          // only sync in the step
        }
    }

    // h_last appended after outputs
    ((u64*)(out + (size_t)BB * TT * HH))[(size_t)b * 32 + l] = hpair;
}

extern "C" void kernel_launch(void* const* d_in, const int* in_sizes, int n_in,
                              void* d_out, int out_size) {
    (void)in_sizes; (void)n_in; (void)out_size;
    const float* x    = (const float*)d_in[0];
    // d_in[1] = seq_lengths: forward no-op (mask only gates gradients)
    const float* W_in = (const float*)d_in[2];
    const float* b_in = (const float*)d_in[3];
    const float* W_hh = (const float*)d_in[4];
    const float* b_hh = (const float*)d_in[5];
    float* out = (float*)d_out;

    xproj_kernel<<<XP_CTAS, XP_THREADS>>>(x, W_in, b_in, b_hh);
    ctrnn_scan_kernel<<<BB, 32>>>(W_hh, out);
}

// round 8
// speedup vs baseline: 2.3472x; 1.1026x over previous
#include <cuda_runtime.h>

// CTRNN forward on GB300 — round 5: k-packed f32x2 everywhere (no duplication),
// 2-warp scan (one output per lane), 4-row-MLP input projection pass.
// Inputs (metadata order): x[B,T,D] f32, seq_lengths[B] i32 (forward no-op),
// W_in[H,D] f32, b_in[H] f32, W_hh[H,H] f32, b_hh[H] f32.
// Output: outputs[B,T,H] then h_last[B,H], f32, concatenated flat.

#define BB 256
#define TT 2048
#define DD 32
#define HH 64
#define PF 8   // xp prefetch depth (steps); TT % PF == 0

typedef unsigned long long u64;

// Scratch for xp = ALPHA*(x@W_in^T + b_in + b_hh), [B][T][H], padded by PF rows
// so the scan's ring refill can load unconditionally (pad contents unused).
__device__ __align__(16) float g_xp[(size_t)BB * TT * HH + PF * HH];

__device__ __forceinline__ u64 pack2(float lo, float hi) {
    u64 r; asm("mov.b64 %0, {%1, %2};" : "=l"(r) : "f"(lo), "f"(hi)); return r;
}
__device__ __forceinline__ float2 unpack2(u64 v) {
    float2 f; asm("mov.b64 {%0, %1}, %2;" : "=f"(f.x), "=f"(f.y) : "l"(v)); return f;
}
// Packed fp32x2 FMA (Blackwell FFMA2): d = a*b + d.
__device__ __forceinline__ void ffma2(u64& d, u64 a, u64 b) {
    asm("fma.rn.f32x2 %0, %1, %2, %0;" : "+l"(d) : "l"(a), "l"(b));
}
__device__ __forceinline__ u64 add2(u64 a, u64 b) {
    u64 r; asm("add.rn.f32x2 %0, %1, %2;" : "=l"(r) : "l"(a), "l"(b)); return r;
}

#define ALPHA_F ((float)(16.67 / 40.0))
#define OMA_F   ((float)(1.0 - 16.67 / 40.0))

#define XP_CTAS    2048
#define XP_THREADS 256
#define XP_WARPS   (XP_CTAS * XP_THREADS / 32)   // 16384 warps
#define XP_ROWS    (BB * TT)                     // 524288 rows
#define XP_RPI     4                             // rows in flight per warp

// ---------------- Pass 1: xp[r,j] = ALPHA*(x[r,:] . W_in[j,:] + b_in[j] + b_hh[j])
// One warp per row group; lane owns outputs (2l, 2l+1), packed along k:
// an x float-pair in memory IS an f32x2 operand (no repacking).
__global__ void __launch_bounds__(XP_THREADS) xproj_kernel(
    const float* __restrict__ x,
    const float* __restrict__ W_in,
    const float* __restrict__ b_in,
    const float* __restrict__ b_hh)
{
    const int gwarp = (blockIdx.x * XP_THREADS + threadIdx.x) >> 5;
    const int l     = threadIdx.x & 31;
    const int j0    = 2 * l, j1 = 2 * l + 1;

    // K-pair weights: w0[k] = (a*W_in[j0][2k], a*W_in[j0][2k+1]); same for j1.
    u64 w0[DD / 2], w1[DD / 2];
    #pragma unroll
    for (int k4 = 0; k4 < DD / 4; k4++) {
        float4 a = ((const float4*)(W_in + j0 * DD))[k4];
        float4 c = ((const float4*)(W_in + j1 * DD))[k4];
        w0[2 * k4]     = pack2(ALPHA_F * a.x, ALPHA_F * a.y);
        w0[2 * k4 + 1] = pack2(ALPHA_F * a.z, ALPHA_F * a.w);
        w1[2 * k4]     = pack2(ALPHA_F * c.x, ALPHA_F * c.y);
        w1[2 * k4 + 1] = pack2(ALPHA_F * c.z, ALPHA_F * c.w);
    }
    const float bias0 = ALPHA_F * (b_in[j0] + b_hh[j0]);
    const float bias1 = ALPHA_F * (b_in[j1] + b_hh[j1]);

    u64* xpw = (u64*)g_xp;

    for (int r = gwarp; r < XP_ROWS; r += XP_RPI * XP_WARPS) {
        #pragma unroll
        for (int rr = 0; rr < XP_RPI; rr++) {
            const int row = r + rr * XP_WARPS;
            // x row as ready-made f32x2 pairs (uniform address -> broadcast LDG.128)
            const ulonglong2* xv = (const ulonglong2*)(x + (size_t)row * DD);
            u64 a0 = 0, a1 = 0, b0 = 0, b1 = 0;
            #pragma unroll
            for (int i = 0; i < DD / 4; i++) {   // 8 x LDG.128, 32 x ffma2
                ulonglong2 q = xv[i];
                ffma2(a0, q.x, w0[2 * i]);
                ffma2(b0, q.x, w1[2 * i]);
                ffma2(a1, q.y, w0[2 * i + 1]);
                ffma2(b1, q.y, w1[2 * i + 1]);
            }
            float2 s0 = unpack2(add2(a0, a1));
            float2 s1 = unpack2(add2(b0, b1));
            xpw[(size_t)row * 32 + l] =
                pack2(s0.x + s0.y + bias0, s1.x + s1.y + bias1);  // STG.64
        }
    }
}

// ---------------- Pass 2: 2-warp scan, one output per lane (j = threadIdx.x).
__global__ void __launch_bounds__(HH) ctrnn_scan_kernel(
    const float* __restrict__ W_hh,
    float* __restrict__ out)
{
    const int b = blockIdx.x;
    const int j = threadIdx.x;     // output index 0..63

    __shared__ __align__(16) float hbuf[2][HH];  // plain h, double-buffered

    // K-pair weights for output j: wk[k] = (a*W[j][2k], a*W[j][2k+1]); 32 u64.
    u64 wk[HH / 2];
    #pragma unroll
    for (int k4 = 0; k4 < HH / 4; k4++) {
        float4 v = ((const float4*)(W_hh + j * HH))[k4];
        wk[2 * k4]     = pack2(ALPHA_F * v.x, ALPHA_F * v.y);
        wk[2 * k4 + 1] = pack2(ALPHA_F * v.z, ALPHA_F * v.w);
    }

    // xp prefetch ring: one float per lane per step (bias already folded in).
    const float* xpb = g_xp + (size_t)b * TT * HH;
    float xr[PF];
    #pragma unroll
    for (int p = 0; p < PF; p++) xr[p] = xpb[p * HH + j];

    hbuf[0][j] = 0.0f;
    float hold = 0.0f;
    __syncthreads();

    float* outb = out + (size_t)b * TT * HH;

    for (int t0 = 0; t0 < TT; t0 += PF) {
        #pragma unroll
        for (int p = 0; p < PF; p++) {
            const int t   = t0 + p;
            const int cur = t & 1;
            const int nxt = cur ^ 1;

            // acc = xp(t) + h(t-1) . (ALPHA*W_hh[j,:]), packed along k.
            // h float-pairs in smem ARE f32x2 operands: 16 LDS.128, 32 ffma2.
            u64 a0 = pack2(xr[p], 0.0f), a1 = 0, a2 = 0, a3 = 0;
            const ulonglong2* hv = (const ulonglong2*)hbuf[cur];  // broadcast
            #pragma unroll
            for (int i = 0; i < HH / 4; i++) {
                ulonglong2 hq = hv[i];
                if (i & 1) { ffma2(a2, hq.x, wk[2 * i]); ffma2(a3, hq.y, wk[2 * i + 1]); }
                else       { ffma2(a0, hq.x, wk[2 * i]); ffma2(a1, hq.y, wk[2 * i + 1]); }
            }
            float2 sf = unpack2(add2(add2(a0, a1), add2(a2, a3)));
            float hnew = fmaxf(fmaf(hold, OMA_F, sf.x + sf.y), 0.0f);

            outb[(size_t)t * HH + j] = hnew;   // coalesced STG.32
            hbuf[nxt][j] = hnew;               // STS.32

            // Refill ring slot with xp(t+PF). Unconditional: g_xp padded by PF
            // rows; values loaded past TT are never consumed.
            xr[p] = xpb[(size_t)(t + PF) * HH + j];

            hold = hnew;
            __syncthreads();                   // one 2-warp barrier per step
        }
    }

    out[(size_t)BB * TT * HH + (size_t)b * HH + j] = hold;
}

extern "C" void kernel_launch(void* const* d_in, const int* in_sizes, int n_in,
                              void* d_out, int out_size) {
    (void)in_sizes; (void)n_in; (void)out_size;
    const float* x    = (const float*)d_in[0];
    // d_in[1] = seq_lengths: forward no-op (mask only gates gradients)
    const float* W_in = (const float*)d_in[2];
    const float* b_in = (const float*)d_in[3];
    const float* W_hh = (const float*)d_in[4];
    const float* b_hh = (const float*)d_in[5];
    float* out = (float*)d_out;

    xproj_kernel<<<XP_CTAS, XP_THREADS>>>(x, W_in, b_in, b_hh);
    ctrnn_scan_kernel<<<BB, HH>>>(W_hh, out);
}

// round 9
// speedup vs baseline: 2.7130x; 1.1558x over previous
#include <cuda_runtime.h>

// CTRNN forward on GB300 — round 6: fully fused single kernel.
// Consumer warps (0-1) run the serial scan step (named barrier, 1 output/lane);
// producer warps (2-3, disjoint SMSPs) compute the input projection into a
// double-buffered smem ring, one 8-step batch ahead, x staged 2 batches ahead.
// Inputs (metadata order): x[B,T,D] f32, seq_lengths[B] i32 (forward no-op),
// W_in[H,D] f32, b_in[H] f32, W_hh[H,H] f32, b_hh[H] f32.
// Output: outputs[B,T,H] then h_last[B,H], f32, concatenated flat.

#define BB 256
#define TT 2048
#define DD 32
#define HH 64
#define PF 8                 // steps per batch; TT % PF == 0
#define NB (TT / PF)         // 256 batches

typedef unsigned long long u64;

__device__ __forceinline__ u64 pack2(float lo, float hi) {
    u64 r; asm("mov.b64 %0, {%1, %2};" : "=l"(r) : "f"(lo), "f"(hi)); return r;
}
__device__ __forceinline__ float2 unpack2(u64 v) {
    float2 f; asm("mov.b64 {%0, %1}, %2;" : "=f"(f.x), "=f"(f.y) : "l"(v)); return f;
}
// Packed fp32x2 FMA (Blackwell FFMA2): d = a*b + d.
__device__ __forceinline__ void ffma2(u64& d, u64 a, u64 b) {
    asm("fma.rn.f32x2 %0, %1, %2, %0;" : "+l"(d) : "l"(a), "l"(b));
}
__device__ __forceinline__ u64 add2(u64 a, u64 b) {
    u64 r; asm("add.rn.f32x2 %0, %1, %2;" : "=l"(r) : "l"(a), "l"(b)); return r;
}

#define ALPHA_F ((float)(16.67 / 40.0))
#define OMA_F   ((float)(1.0 - 16.67 / 40.0))

// Consumer-only named barrier (threads 0..63 = warps 0,1).
#define CONSUMER_BAR() asm volatile("bar.sync 1, 64;" ::: "memory")

__global__ void __launch_bounds__(128) ctrnn_fused_kernel(
    const float* __restrict__ x,
    const float* __restrict__ W_in,
    const float* __restrict__ b_in,
    const float* __restrict__ W_hh,
    const float* __restrict__ b_hh,
    float* __restrict__ out)
{
    const int b   = blockIdx.x;
    const int tid = threadIdx.x;

    __shared__ __align__(16) float hbuf[2][HH];           // hidden state, dbl-buf
    __shared__ __align__(16) float xpring[2][PF][HH];     // xp batches, dbl-buf
    __shared__ __align__(16) float xstage[2][PF][DD];     // raw x batches, dbl-buf

    const bool is_consumer = (tid < HH);
    const float* xb = x + (size_t)b * TT * DD;

    // ---------------- role-specific register setup (no barriers here) ----------
    u64 wk[HH / 2];        // consumer: ALPHA*W_hh row j, k-packed
    u64 wi[DD / 2];        // producer: ALPHA*W_in row pj, k-packed
    float biasj = 0.0f;
    const int j  = tid;          // consumer output index (valid if tid<64)
    const int pj = tid - HH;     // producer output index (valid if tid>=64)

    if (is_consumer) {
        #pragma unroll
        for (int k4 = 0; k4 < HH / 4; k4++) {
            float4 v = ((const float4*)(W_hh + j * HH))[k4];
            wk[2 * k4]     = pack2(ALPHA_F * v.x, ALPHA_F * v.y);
            wk[2 * k4 + 1] = pack2(ALPHA_F * v.z, ALPHA_F * v.w);
        }
        hbuf[0][j] = 0.0f;
    } else {
        #pragma unroll
        for (int k4 = 0; k4 < DD / 4; k4++) {
            float4 v = ((const float4*)(W_in + pj * DD))[k4];
            wi[2 * k4]     = pack2(ALPHA_F * v.x, ALPHA_F * v.y);
            wi[2 * k4 + 1] = pack2(ALPHA_F * v.z, ALPHA_F * v.w);
        }
        biasj = ALPHA_F * (b_in[pj] + b_hh[pj]);
    }

    // Producer staging map: lane (tid-64) = idx 0..63 loads float4 #idx of a
    // batch: row r = idx>>3 (0..7), quad q = idx&7 -> but DD=32 floats = 8
    // float4 per row: so r = idx>>3, q = idx&7.
    const int sr = pj >> 3;          // staging row     (producers only)
    const int sq = pj & 7;           // staging quad

    // ---------------- prologue: stage x batch 0; produce xp batch 0; stage x batch 1
    if (!is_consumer) {
        float4 v = ((const float4*)(xb + (size_t)(0 * PF + sr) * DD))[sq];
        ((float4*)xstage[0][sr])[sq] = v;
    }
    __syncthreads();   // S0: xstage[0] visible to all producers

    if (!is_consumer) {
        // produce xp batch 0 -> xpring[0]
        #pragma unroll
        for (int r = 0; r < PF; r++) {
            const ulonglong2* xv = (const ulonglong2*)xstage[0][r];   // broadcast
            u64 a0 = pack2(biasj, 0.0f), a1 = 0;
            #pragma unroll
            for (int i = 0; i < DD / 4; i++) {
                ulonglong2 q = xv[i];
                ffma2(a0, q.x, wi[2 * i]);
                ffma2(a1, q.y, wi[2 * i + 1]);
            }
            float2 s = unpack2(add2(a0, a1));
            xpring[0][r][pj] = s.x + s.y;
        }
        // stage x batch 1 -> xstage[1]
        float4 v = ((const float4*)(xb + (size_t)(1 * PF + sr) * DD))[sq];
        ((float4*)xstage[1][sr])[sq] = v;
    }
    __syncthreads();   // S1: xpring[0] + xstage[1] valid; scan may start

    float hold = 0.0f;
    float* outb = out + (size_t)b * TT * HH;

    // ---------------- main loop over batches ----------------------------------
    for (int n = 0; n < NB; n++) {
        const int rb = n & 1;

        if (is_consumer) {
            float xpv = xpring[rb][0][j];              // LDS after batch swap
            #pragma unroll
            for (int p = 0; p < PF; p++) {
                const int t   = n * PF + p;
                const int cur = t & 1;

                // acc = xp(t) + h(t-1) . (ALPHA*W_hh[j,:]), k-packed:
                // 16 LDS.128 (broadcast) + 32 ffma2.
                u64 a0 = pack2(xpv, 0.0f), a1 = 0, a2 = 0, a3 = 0;
                const ulonglong2* hv = (const ulonglong2*)hbuf[cur];
                #pragma unroll
                for (int i = 0; i < HH / 4; i++) {
                    ulonglong2 hq = hv[i];
                    if (i & 1) { ffma2(a2, hq.x, wk[2 * i]); ffma2(a3, hq.y, wk[2 * i + 1]); }
                    else       { ffma2(a0, hq.x, wk[2 * i]); ffma2(a1, hq.y, wk[2 * i + 1]); }
                }
                float2 sf = unpack2(add2(add2(a0, a1), add2(a2, a3)));
                float hnew = fmaxf(fmaf(hold, OMA_F, sf.x + sf.y), 0.0f);

                outb[(size_t)t * HH + j] = hnew;       // coalesced STG.32
                hbuf[cur ^ 1][j] = hnew;               // STS.32
                hold = hnew;

                if (p < PF - 1) {
                    xpv = xpring[rb][p + 1][j];        // prefetch next xp
                    CONSUMER_BAR();                    // 2-warp named barrier
                }
                // p == PF-1: the CTA __syncthreads below is the step barrier.
            }
        } else {
            // Producers: compute xp batch n+1; stage x batch n+2.
            if (n + 1 < NB) {
                const int cb = (n + 1) & 1;
                #pragma unroll
                for (int r = 0; r < PF; r++) {
                    const ulonglong2* xv = (const ulonglong2*)xstage[cb][r];
                    u64 a0 = pack2(biasj, 0.0f), a1 = 0;
                    #pragma unroll
                    for (int i = 0; i < DD / 4; i++) {
                        ulonglong2 q = xv[i];
                        ffma2(a0, q.x, wi[2 * i]);
                        ffma2(a1, q.y, wi[2 * i + 1]);
                    }
                    float2 s = unpack2(add2(a0, a1));
                    xpring[cb][r][pj] = s.x + s.y;
                }
            }
            if (n + 2 < NB) {
                float4 v = ((const float4*)(xb + (size_t)((n + 2) * PF + sr) * DD))[sq];
                ((float4*)xstage[n & 1][sr])[sq] = v;
            }
        }

        __syncthreads();   // batch swap: ring/stage handoff + consumer step barrier
    }

    if (is_consumer)
        out[(size_t)BB * TT * HH + (size_t)b * HH + j] = hold;
}

extern "C" void kernel_launch(void* const* d_in, const int* in_sizes, int n_in,
                              void* d_out, int out_size) {
    (void)in_sizes; (void)n_in; (void)out_size;
    const float* x    = (const float*)d_in[0];
    // d_in[1] = seq_lengths: forward no-op (mask only gates gradients)
    const float* W_in = (const float*)d_in[2];
    const float* b_in = (const float*)d_in[3];
    const float* W_hh = (const float*)d_in[4];
    const float* b_hh = (const float*)d_in[5];

    ctrnn_fused_kernel<<<BB, 128>>>(x, W_in, b_in, W_hh, b_hh, (float*)d_out);
}